// round 13
// baseline (speedup 1.0000x reference)
#include <cuda_runtime.h>
#include <cstdint>

#define D_MODEL   1024
#define NUM_HEADS 16
#define HEAD_DIM  64
#define BATCH     2
#define SEQ       2048
#define MTOT      (BATCH * SEQ)   /* 4096 rows */

// ---------------------------------------------------------------------------
// Scratch (device globals; no allocation allowed)
// ---------------------------------------------------------------------------
__device__ float g_q[MTOT * D_MODEL];
__device__ float g_k[MTOT * D_MODEL];
__device__ float g_v[MTOT * D_MODEL];
__device__ float g_o[MTOT * D_MODEL];

__device__ __forceinline__ uint32_t f2tf32(float f) {
    uint32_t r;
    asm("cvt.rna.tf32.f32 %0, %1;" : "=r"(r) : "f"(f));
    return r;
}

__device__ __forceinline__ void mma_tf32(
    float& c0, float& c1, float& c2, float& c3,
    uint32_t a0, uint32_t a1, uint32_t a2, uint32_t a3,
    uint32_t b0, uint32_t b1)
{
    asm volatile(
        "mma.sync.aligned.m16n8k8.row.col.f32.tf32.tf32.f32 "
        "{%0,%1,%2,%3}, {%4,%5,%6,%7}, {%8,%9}, {%0,%1,%2,%3};"
        : "+f"(c0), "+f"(c1), "+f"(c2), "+f"(c3)
        : "r"(a0), "r"(a1), "r"(a2), "r"(a3), "r"(b0), "r"(b1));
}

// ---------------------------------------------------------------------------
// TF32 tensor-core GEMM:  C[M,N] = A[M,K] @ B[N,K]^T  (row-major, K contig)
// Block tile 128x128, BK=32, 256 threads (8 warps as 4x2, warp tile 32x64).
// Double-buffered smem + register prefetch; ONE barrier per K-iteration.
// ---------------------------------------------------------------------------
#define GBM 128
#define GBN 128
#define GBK 32
#define LDS_K 36   /* padded smem stride (words): 32 + 4 */

#define GEMM_BUF_WORDS (2 * GBM * LDS_K)            /* As+Bs per buffer */
#define GEMM_SMEM_BYTES (2 * GEMM_BUF_WORDS * 4)    /* 73728 B */

__device__ __forceinline__ void gemm_ldg(
    const float* __restrict__ A, const float* __restrict__ B,
    int m0, int n0, int K, int k0, int tid, float4* pa, float4* pb)
{
    #pragma unroll
    for (int i = 0; i < 4; i++) {
        int e  = tid + i * 256;
        int r  = e >> 3;
        int c4 = (e & 7) * 4;
        pa[i] = *(const float4*)&A[(size_t)(m0 + r) * K + k0 + c4];
        pb[i] = *(const float4*)&B[(size_t)(n0 + r) * K + k0 + c4];
    }
}

__device__ __forceinline__ void gemm_sts(
    uint32_t* As, uint32_t* Bs, int tid, const float4* pa, const float4* pb)
{
    #pragma unroll
    for (int i = 0; i < 4; i++) {
        int e  = tid + i * 256;
        int r  = e >> 3;
        int c4 = (e & 7) * 4;
        *(uint4*)&As[r * LDS_K + c4] =
            make_uint4(f2tf32(pa[i].x), f2tf32(pa[i].y), f2tf32(pa[i].z), f2tf32(pa[i].w));
        *(uint4*)&Bs[r * LDS_K + c4] =
            make_uint4(f2tf32(pb[i].x), f2tf32(pb[i].y), f2tf32(pb[i].z), f2tf32(pb[i].w));
    }
}

__global__ __launch_bounds__(256, 2) void gemm_tf32_kernel(
    const float* __restrict__ A, const float* __restrict__ B,
    float* __restrict__ C, int M, int N, int K)
{
    extern __shared__ uint32_t gsm[];

    const int tid     = threadIdx.x;
    const int lane    = tid & 31;
    const int warp    = tid >> 5;
    const int groupID = lane >> 2;
    const int tig     = lane & 3;

    const int m0 = blockIdx.y * GBM;
    const int n0 = blockIdx.x * GBN;
    const int m_warp = (warp >> 1) * 32;
    const int n_warp = (warp & 1) * 64;

    uint32_t* AsBuf[2] = { gsm,                gsm + GEMM_BUF_WORDS };
    uint32_t* BsBuf[2] = { gsm + GBM * LDS_K,  gsm + GEMM_BUF_WORDS + GBM * LDS_K };

    float acc[2][8][4];
    #pragma unroll
    for (int mt = 0; mt < 2; mt++)
        #pragma unroll
        for (int nt = 0; nt < 8; nt++)
            #pragma unroll
            for (int c = 0; c < 4; c++) acc[mt][nt][c] = 0.0f;

    float4 pa[4], pb[4];
    gemm_ldg(A, B, m0, n0, K, 0, tid, pa, pb);
    gemm_sts(AsBuf[0], BsBuf[0], tid, pa, pb);
    __syncthreads();

    const int nk = K / GBK;
    for (int kt = 0; kt < nk; kt++) {
        if (kt + 1 < nk)
            gemm_ldg(A, B, m0, n0, K, (kt + 1) * GBK, tid, pa, pb);

        const uint32_t* cA = AsBuf[kt & 1];
        const uint32_t* cB = BsBuf[kt & 1];

        #pragma unroll
        for (int kk8 = 0; kk8 < GBK / 8; kk8++) {
            const int kb = kk8 * 8;

            uint32_t a[2][4];
            #pragma unroll
            for (int mt = 0; mt < 2; mt++) {
                int r = m_warp + mt * 16 + groupID;
                a[mt][0] = cA[(r    ) * LDS_K + kb + tig    ];
                a[mt][1] = cA[(r + 8) * LDS_K + kb + tig    ];
                a[mt][2] = cA[(r    ) * LDS_K + kb + tig + 4];
                a[mt][3] = cA[(r + 8) * LDS_K + kb + tig + 4];
            }

            uint32_t b[8][2];
            #pragma unroll
            for (int nt = 0; nt < 8; nt++) {
                int r = n_warp + nt * 8 + groupID;
                b[nt][0] = cB[r * LDS_K + kb + tig    ];
                b[nt][1] = cB[r * LDS_K + kb + tig + 4];
            }

            #pragma unroll
            for (int mt = 0; mt < 2; mt++)
                #pragma unroll
                for (int nt = 0; nt < 8; nt++)
                    mma_tf32(acc[mt][nt][0], acc[mt][nt][1],
                             acc[mt][nt][2], acc[mt][nt][3],
                             a[mt][0], a[mt][1], a[mt][2], a[mt][3],
                             b[nt][0], b[nt][1]);
        }

        if (kt + 1 < nk)
            gemm_sts(AsBuf[(kt + 1) & 1], BsBuf[(kt + 1) & 1], tid, pa, pb);
        __syncthreads();
    }

    #pragma unroll
    for (int mt = 0; mt < 2; mt++) {
        int row = m0 + m_warp + mt * 16 + groupID;
        #pragma unroll
        for (int nt = 0; nt < 8; nt++) {
            int col = n0 + n_warp + nt * 8 + tig * 2;
            *(float2*)&C[(size_t)(row    ) * N + col] =
                make_float2(acc[mt][nt][0], acc[mt][nt][1]);
            *(float2*)&C[(size_t)(row + 8) * N + col] =
                make_float2(acc[mt][nt][2], acc[mt][nt][3]);
        }
    }
}

// ---------------------------------------------------------------------------
// Tensor-core flash attention (tf32 mma, fp32 softmax/accumulators).
// CTA = 128 q-rows x (head, batch). 8 warps; warp owns 16 rows.
// KV tile = 64. Register prefetch of the next KV tile overlaps the full
// compute phase (QK mma + softmax + PV mma).
// ---------------------------------------------------------------------------
#define AQT  128
#define AKT  64
#define ALD  68   /* padded word stride: 64 + 4 */

#define ATTN_SMEM_WORDS (2 * AKT * ALD + AQT * ALD)
#define ATTN_SMEM_BYTES (ATTN_SMEM_WORDS * 4)

__device__ __forceinline__ void attn_ldg(
    const float* __restrict__ K, const float* __restrict__ V,
    size_t base, int kt, int tid, float4* pk, float4* pv)
{
    #pragma unroll
    for (int i = 0; i < 4; i++) {
        int e  = tid + i * 256;
        int r  = e >> 4;
        int c4 = (e & 15) * 4;
        size_t gaddr = base + (size_t)(kt * AKT + r) * D_MODEL + c4;
        pk[i] = *(const float4*)&K[gaddr];
        pv[i] = *(const float4*)&V[gaddr];
    }
}

__device__ __forceinline__ void attn_sts(
    uint32_t* Ks, uint32_t* Vt, int tid, const float4* pk, const float4* pv)
{
    #pragma unroll
    for (int i = 0; i < 4; i++) {
        int e  = tid + i * 256;
        int r  = e >> 4;
        int c4 = (e & 15) * 4;
        uint32_t* kd = &Ks[r * ALD + c4];
        kd[0] = f2tf32(pk[i].x); kd[1] = f2tf32(pk[i].y);
        kd[2] = f2tf32(pk[i].z); kd[3] = f2tf32(pk[i].w);
        Vt[(c4 + 0) * ALD + r] = f2tf32(pv[i].x);
        Vt[(c4 + 1) * ALD + r] = f2tf32(pv[i].y);
        Vt[(c4 + 2) * ALD + r] = f2tf32(pv[i].z);
        Vt[(c4 + 3) * ALD + r] = f2tf32(pv[i].w);
    }
}

__global__ __launch_bounds__(256, 2) void attn_mma_kernel(
    const float* __restrict__ Q, const float* __restrict__ K,
    const float* __restrict__ V, float* __restrict__ O)
{
    extern __shared__ uint32_t sm[];
    uint32_t* Ks = sm;                    // [64][68]  k-rows x d
    uint32_t* Vt = Ks + AKT * ALD;        // [64][68]  d x kv (transposed)
    uint32_t* Ps = Vt + AKT * ALD;        // [128][68] q-rows x kv

    const int qtile = (int)gridDim.x - 1 - (int)blockIdx.x;  // heavy tiles first
    const int h    = blockIdx.y;
    const int b    = blockIdx.z;
    const int tid  = threadIdx.x;
    const int lane = tid & 31;
    const int warp = tid >> 5;
    const int g    = lane >> 2;
    const int tig  = lane & 3;
    const int wrow = warp * 16;

    const size_t base = (size_t)b * SEQ * D_MODEL + (size_t)h * HEAD_DIM;
    const int q0 = qtile * AQT;

    // Q fragments, pre-scaled by 1/sqrt(HEAD_DIM)
    uint32_t qf[8][4];
    {
        const float* Qr0 = Q + base + (size_t)(q0 + wrow + g) * D_MODEL;
        const float* Qr1 = Qr0 + 8 * D_MODEL;
        #pragma unroll
        for (int k8 = 0; k8 < 8; k8++) {
            qf[k8][0] = f2tf32(0.125f * Qr0[k8 * 8 + tig]);
            qf[k8][1] = f2tf32(0.125f * Qr1[k8 * 8 + tig]);
            qf[k8][2] = f2tf32(0.125f * Qr0[k8 * 8 + tig + 4]);
            qf[k8][3] = f2tf32(0.125f * Qr1[k8 * 8 + tig + 4]);
        }
    }

    float o[8][4];
    #pragma unroll
    for (int nt = 0; nt < 8; nt++)
        #pragma unroll
        for (int c = 0; c < 4; c++) o[nt][c] = 0.0f;

    float m0 = -1e30f, m1 = -1e30f, l0 = 0.0f, l1 = 0.0f;

    float4 pk[4], pv[4];
    attn_ldg(K, V, base, 0, tid, pk, pv);

    const int ktmax = 2 * qtile + 1;
    for (int kt = 0; kt <= ktmax; kt++) {
        // --- stage prefetched K/V tile into smem ---
        attn_sts(Ks, Vt, tid, pk, pv);
        __syncthreads();

        // --- issue next tile's loads; latency hides under compute below ---
        if (kt < ktmax)
            attn_ldg(K, V, base, kt + 1, tid, pk, pv);

        // --- S = (Q*scale) @ K^T ---
        float s[8][4];
        #pragma unroll
        for (int nt = 0; nt < 8; nt++)
            #pragma unroll
            for (int c = 0; c < 4; c++) s[nt][c] = 0.0f;

        #pragma unroll
        for (int k8 = 0; k8 < 8; k8++) {
            #pragma unroll
            for (int nt = 0; nt < 8; nt++) {
                uint32_t b0 = Ks[(nt * 8 + g) * ALD + k8 * 8 + tig    ];
                uint32_t b1 = Ks[(nt * 8 + g) * ALD + k8 * 8 + tig + 4];
                mma_tf32(s[nt][0], s[nt][1], s[nt][2], s[nt][3],
                         qf[k8][0], qf[k8][1], qf[k8][2], qf[k8][3], b0, b1);
            }
        }

        // --- causal mask (only diagonal-adjacent tiles) ---
        if (kt >= 2 * qtile) {
            int qr0 = q0 + wrow + g;
            int qr1 = qr0 + 8;
            #pragma unroll
            for (int nt = 0; nt < 8; nt++) {
                int c = kt * AKT + nt * 8 + tig * 2;
                if (c     > qr0) s[nt][0] = -1e30f;
                if (c + 1 > qr0) s[nt][1] = -1e30f;
                if (c     > qr1) s[nt][2] = -1e30f;
                if (c + 1 > qr1) s[nt][3] = -1e30f;
            }
        }

        // --- online softmax (rows g and g+8; quad shuffle) ---
        float mt0 = -1e30f, mt1 = -1e30f;
        #pragma unroll
        for (int nt = 0; nt < 8; nt++) {
            mt0 = fmaxf(mt0, fmaxf(s[nt][0], s[nt][1]));
            mt1 = fmaxf(mt1, fmaxf(s[nt][2], s[nt][3]));
        }
        #pragma unroll
        for (int off = 1; off <= 2; off <<= 1) {
            mt0 = fmaxf(mt0, __shfl_xor_sync(0xffffffffu, mt0, off));
            mt1 = fmaxf(mt1, __shfl_xor_sync(0xffffffffu, mt1, off));
        }

        float mn0 = fmaxf(m0, mt0);
        float mn1 = fmaxf(m1, mt1);
        float alpha0 = __expf(m0 - mn0);
        float alpha1 = __expf(m1 - mn1);
        m0 = mn0; m1 = mn1;

        float ps0 = 0.0f, ps1 = 0.0f;
        #pragma unroll
        for (int nt = 0; nt < 8; nt++) {
            s[nt][0] = __expf(s[nt][0] - mn0);
            s[nt][1] = __expf(s[nt][1] - mn0);
            s[nt][2] = __expf(s[nt][2] - mn1);
            s[nt][3] = __expf(s[nt][3] - mn1);
            ps0 += s[nt][0] + s[nt][1];
            ps1 += s[nt][2] + s[nt][3];
        }
        #pragma unroll
        for (int off = 1; off <= 2; off <<= 1) {
            ps0 += __shfl_xor_sync(0xffffffffu, ps0, off);
            ps1 += __shfl_xor_sync(0xffffffffu, ps1, off);
        }
        l0 = l0 * alpha0 + ps0;
        l1 = l1 * alpha1 + ps1;

        #pragma unroll
        for (int nt = 0; nt < 8; nt++) {
            o[nt][0] *= alpha0; o[nt][1] *= alpha0;
            o[nt][2] *= alpha1; o[nt][3] *= alpha1;
        }

        // --- write P to smem (tf32 bits), re-enter as A operand ---
        {
            uint32_t* pr0 = &Ps[(wrow + g    ) * ALD];
            uint32_t* pr1 = &Ps[(wrow + g + 8) * ALD];
            #pragma unroll
            for (int nt = 0; nt < 8; nt++) {
                int c = nt * 8 + tig * 2;
                pr0[c    ] = f2tf32(s[nt][0]);
                pr0[c + 1] = f2tf32(s[nt][1]);
                pr1[c    ] = f2tf32(s[nt][2]);
                pr1[c + 1] = f2tf32(s[nt][3]);
            }
        }
        __syncwarp();   // own-warp cross-lane STS->LDS visibility

        // --- O += P @ V ---
        #pragma unroll
        for (int k8 = 0; k8 < 8; k8++) {
            uint32_t af0 = Ps[(wrow + g    ) * ALD + k8 * 8 + tig    ];
            uint32_t af1 = Ps[(wrow + g + 8) * ALD + k8 * 8 + tig    ];
            uint32_t af2 = Ps[(wrow + g    ) * ALD + k8 * 8 + tig + 4];
            uint32_t af3 = Ps[(wrow + g + 8) * ALD + k8 * 8 + tig + 4];
            #pragma unroll
            for (int nt = 0; nt < 8; nt++) {
                uint32_t b0 = Vt[(nt * 8 + g) * ALD + k8 * 8 + tig    ];
                uint32_t b1 = Vt[(nt * 8 + g) * ALD + k8 * 8 + tig + 4];
                mma_tf32(o[nt][0], o[nt][1], o[nt][2], o[nt][3],
                         af0, af1, af2, af3, b0, b1);
            }
        }
        __syncthreads();   // protect Ks/Vt before next tile's staging
    }

    // --- finalize ---
    float inv0 = 1.0f / l0;
    float inv1 = 1.0f / l1;
    float* Or0 = O + base + (size_t)(q0 + wrow + g) * D_MODEL;
    float* Or1 = Or0 + 8 * D_MODEL;
    #pragma unroll
    for (int nt = 0; nt < 8; nt++) {
        int c = nt * 8 + tig * 2;
        *(float2*)&Or0[c] = make_float2(o[nt][0] * inv0, o[nt][1] * inv0);
        *(float2*)&Or1[c] = make_float2(o[nt][2] * inv1, o[nt][3] * inv1);
    }
}

// ---------------------------------------------------------------------------
// Launch
// ---------------------------------------------------------------------------
extern "C" void kernel_launch(void* const* d_in, const int* in_sizes, int n_in,
                              void* d_out, int out_size)
{
    const float* x  = (const float*)d_in[0];
    const float* Wq = (const float*)d_in[1];
    const float* Wk = (const float*)d_in[2];
    const float* Wv = (const float*)d_in[3];
    const float* Wo = (const float*)d_in[4];
    float* out = (float*)d_out;

    float *q, *k, *v, *o;
    cudaGetSymbolAddress((void**)&q, g_q);
    cudaGetSymbolAddress((void**)&k, g_k);
    cudaGetSymbolAddress((void**)&v, g_v);
    cudaGetSymbolAddress((void**)&o, g_o);

    cudaFuncSetAttribute(gemm_tf32_kernel,
                         cudaFuncAttributeMaxDynamicSharedMemorySize,
                         GEMM_SMEM_BYTES);
    cudaFuncSetAttribute(attn_mma_kernel,
                         cudaFuncAttributeMaxDynamicSharedMemorySize,
                         ATTN_SMEM_BYTES);

    dim3 gemm_grid(D_MODEL / GBN, MTOT / GBM);   // (8, 32)
    dim3 blk(256);

    gemm_tf32_kernel<<<gemm_grid, blk, GEMM_SMEM_BYTES>>>(x, Wq, q, MTOT, D_MODEL, D_MODEL);
    gemm_tf32_kernel<<<gemm_grid, blk, GEMM_SMEM_BYTES>>>(x, Wk, k, MTOT, D_MODEL, D_MODEL);
    gemm_tf32_kernel<<<gemm_grid, blk, GEMM_SMEM_BYTES>>>(x, Wv, v, MTOT, D_MODEL, D_MODEL);

    dim3 attn_grid(SEQ / AQT, NUM_HEADS, BATCH);  // (16, 16, 2)
    attn_mma_kernel<<<attn_grid, blk, ATTN_SMEM_BYTES>>>(q, k, v, o);

    gemm_tf32_kernel<<<gemm_grid, blk, GEMM_SMEM_BYTES>>>(o, Wo, out, MTOT, D_MODEL, D_MODEL);
}

// round 14
// speedup vs baseline: 1.2555x; 1.2555x over previous
#include <cuda_runtime.h>
#include <cstdint>

#define D_MODEL   1024
#define NUM_HEADS 16
#define HEAD_DIM  64
#define BATCH     2
#define SEQ       2048
#define MTOT      (BATCH * SEQ)   /* 4096 rows */

// ---------------------------------------------------------------------------
// Scratch (device globals; no allocation allowed)
// ---------------------------------------------------------------------------
__device__ float g_q[MTOT * D_MODEL];
__device__ float g_k[MTOT * D_MODEL];
__device__ float g_v[MTOT * D_MODEL];
__device__ float g_o[MTOT * D_MODEL];

__device__ __forceinline__ uint32_t f2tf32(float f) {
    uint32_t r;
    asm("cvt.rna.tf32.f32 %0, %1;" : "=r"(r) : "f"(f));
    return r;
}

__device__ __forceinline__ void mma_tf32(
    float& c0, float& c1, float& c2, float& c3,
    uint32_t a0, uint32_t a1, uint32_t a2, uint32_t a3,
    uint32_t b0, uint32_t b1)
{
    asm volatile(
        "mma.sync.aligned.m16n8k8.row.col.f32.tf32.tf32.f32 "
        "{%0,%1,%2,%3}, {%4,%5,%6,%7}, {%8,%9}, {%0,%1,%2,%3};"
        : "+f"(c0), "+f"(c1), "+f"(c2), "+f"(c3)
        : "r"(a0), "r"(a1), "r"(a2), "r"(a3), "r"(b0), "r"(b1));
}

// ---------------------------------------------------------------------------
// TF32 tensor-core GEMM:  C[M,N] = A[M,K] @ B[N,K]^T  (row-major, K contig)
// Block tile 128x128, BK=32, 256 threads (8 warps as 4x2, warp tile 32x64).
// Multi-matrix: blockIdx.x >> 3 selects among up to 3 (B, C) pairs so the
// three QKV projections run as ONE work-conserving launch.
// ---------------------------------------------------------------------------
#define GBM 128
#define GBN 128
#define GBK 32
#define LDS_K 36   /* padded smem stride (words): 32 + 4 */

__global__ __launch_bounds__(256, 2) void gemm_tf32_multi(
    const float* __restrict__ A,
    const float* __restrict__ B0, const float* __restrict__ B1,
    const float* __restrict__ B2,
    float* __restrict__ C0, float* __restrict__ C1, float* __restrict__ C2,
    int M, int N, int K)
{
    __shared__ uint32_t As[GBM * LDS_K];
    __shared__ uint32_t Bs[GBN * LDS_K];

    const int w = blockIdx.x >> 3;            // which matrix
    const float* B = (w == 0) ? B0 : (w == 1) ? B1 : B2;
    float*       C = (w == 0) ? C0 : (w == 1) ? C1 : C2;

    const int tid     = threadIdx.x;
    const int lane    = tid & 31;
    const int warp    = tid >> 5;
    const int groupID = lane >> 2;
    const int tig     = lane & 3;

    const int m0 = blockIdx.y * GBM;
    const int n0 = (blockIdx.x & 7) * GBN;
    const int m_warp = (warp >> 1) * 32;
    const int n_warp = (warp & 1) * 64;

    float acc[2][8][4];
    #pragma unroll
    for (int mt = 0; mt < 2; mt++)
        #pragma unroll
        for (int nt = 0; nt < 8; nt++)
            #pragma unroll
            for (int c = 0; c < 4; c++) acc[mt][nt][c] = 0.0f;

    for (int k0 = 0; k0 < K; k0 += GBK) {
        #pragma unroll
        for (int i = 0; i < 4; i++) {
            int e  = tid + i * 256;
            int r  = e >> 3;
            int c4 = (e & 7) * 4;
            float4 av = *(const float4*)&A[(size_t)(m0 + r) * K + k0 + c4];
            float4 bv = *(const float4*)&B[(size_t)(n0 + r) * K + k0 + c4];
            *(uint4*)&As[r * LDS_K + c4] =
                make_uint4(f2tf32(av.x), f2tf32(av.y), f2tf32(av.z), f2tf32(av.w));
            *(uint4*)&Bs[r * LDS_K + c4] =
                make_uint4(f2tf32(bv.x), f2tf32(bv.y), f2tf32(bv.z), f2tf32(bv.w));
        }
        __syncthreads();

        #pragma unroll
        for (int kk8 = 0; kk8 < GBK / 8; kk8++) {
            const int kb = kk8 * 8;

            uint32_t a[2][4];
            #pragma unroll
            for (int mt = 0; mt < 2; mt++) {
                int r = m_warp + mt * 16 + groupID;
                a[mt][0] = As[(r    ) * LDS_K + kb + tig    ];
                a[mt][1] = As[(r + 8) * LDS_K + kb + tig    ];
                a[mt][2] = As[(r    ) * LDS_K + kb + tig + 4];
                a[mt][3] = As[(r + 8) * LDS_K + kb + tig + 4];
            }

            uint32_t b[8][2];
            #pragma unroll
            for (int nt = 0; nt < 8; nt++) {
                int r = n_warp + nt * 8 + groupID;
                b[nt][0] = Bs[r * LDS_K + kb + tig    ];
                b[nt][1] = Bs[r * LDS_K + kb + tig + 4];
            }

            #pragma unroll
            for (int mt = 0; mt < 2; mt++)
                #pragma unroll
                for (int nt = 0; nt < 8; nt++)
                    mma_tf32(acc[mt][nt][0], acc[mt][nt][1],
                             acc[mt][nt][2], acc[mt][nt][3],
                             a[mt][0], a[mt][1], a[mt][2], a[mt][3],
                             b[nt][0], b[nt][1]);
        }
        __syncthreads();
    }

    #pragma unroll
    for (int mt = 0; mt < 2; mt++) {
        int row = m0 + m_warp + mt * 16 + groupID;
        #pragma unroll
        for (int nt = 0; nt < 8; nt++) {
            int col = n0 + n_warp + nt * 8 + tig * 2;
            *(float2*)&C[(size_t)(row    ) * N + col] =
                make_float2(acc[mt][nt][0], acc[mt][nt][1]);
            *(float2*)&C[(size_t)(row + 8) * N + col] =
                make_float2(acc[mt][nt][2], acc[mt][nt][3]);
        }
    }
}

// ---------------------------------------------------------------------------
// Tensor-core flash attention (tf32 mma, fp32 softmax/accumulators).
// CTA = 128 q-rows x (head, batch). 8 warps; warp owns 16 rows.
// K staged [kv][d] stride 68 (QK B-frags conflict-free: banks 4g+tig).
// V staged NATURALLY [kv][d] stride 72 (PV B-frags conflict-free: banks
// 8*tig+g) -- no transpose scatter. Softmax in exp2 domain (log2e folded
// into the Q pre-scale).
// ---------------------------------------------------------------------------
#define AQT   128
#define AKT   64
#define ALDK  68   /* K/P padded word stride: 64 + 4 */
#define ALDV  72   /* V padded word stride: 64 + 8 (stride % 32 == 8) */

#define ATTN_SMEM_WORDS (AKT * ALDK + AKT * ALDV + AQT * ALDK)
#define ATTN_SMEM_BYTES (ATTN_SMEM_WORDS * 4)

__global__ __launch_bounds__(256, 2) void attn_mma_kernel(
    const float* __restrict__ Q, const float* __restrict__ K,
    const float* __restrict__ V, float* __restrict__ O)
{
    extern __shared__ uint32_t sm[];
    uint32_t* Ks = sm;                    // [64][68]  kv x d
    uint32_t* Vs = Ks + AKT * ALDK;       // [64][72]  kv x d (natural)
    uint32_t* Ps = Vs + AKT * ALDV;       // [128][68] q x kv

    const int qtile = (int)gridDim.x - 1 - (int)blockIdx.x;  // heavy tiles first
    const int h    = blockIdx.y;
    const int b    = blockIdx.z;
    const int tid  = threadIdx.x;
    const int lane = tid & 31;
    const int warp = tid >> 5;
    const int g    = lane >> 2;
    const int tig  = lane & 3;
    const int wrow = warp * 16;

    const size_t base = (size_t)b * SEQ * D_MODEL + (size_t)h * HEAD_DIM;
    const int q0 = qtile * AQT;

    // Q fragments, pre-scaled by log2(e)/sqrt(HEAD_DIM) (exp2-domain softmax)
    const float qscale = 0.125f * 1.44269504088896340736f;
    uint32_t qf[8][4];
    {
        const float* Qr0 = Q + base + (size_t)(q0 + wrow + g) * D_MODEL;
        const float* Qr1 = Qr0 + 8 * D_MODEL;
        #pragma unroll
        for (int k8 = 0; k8 < 8; k8++) {
            qf[k8][0] = f2tf32(qscale * Qr0[k8 * 8 + tig]);
            qf[k8][1] = f2tf32(qscale * Qr1[k8 * 8 + tig]);
            qf[k8][2] = f2tf32(qscale * Qr0[k8 * 8 + tig + 4]);
            qf[k8][3] = f2tf32(qscale * Qr1[k8 * 8 + tig + 4]);
        }
    }

    float o[8][4];
    #pragma unroll
    for (int nt = 0; nt < 8; nt++)
        #pragma unroll
        for (int c = 0; c < 4; c++) o[nt][c] = 0.0f;

    float m0 = -1e30f, m1 = -1e30f, l0 = 0.0f, l1 = 0.0f;

    const int ktmax = 2 * qtile + 1;
    for (int kt = 0; kt <= ktmax; kt++) {
        // --- stage K and V tiles (both natural layout, uint4 stores) ---
        #pragma unroll
        for (int i = 0; i < 4; i++) {
            int e  = tid + i * 256;        // 0..1023 float4-slots
            int r  = e >> 4;               // 0..63   kv row
            int c4 = (e & 15) * 4;         // 0..60   d
            size_t gaddr = base + (size_t)(kt * AKT + r) * D_MODEL + c4;
            float4 kv = *(const float4*)&K[gaddr];
            float4 vv = *(const float4*)&V[gaddr];
            *(uint4*)&Ks[r * ALDK + c4] =
                make_uint4(f2tf32(kv.x), f2tf32(kv.y), f2tf32(kv.z), f2tf32(kv.w));
            *(uint4*)&Vs[r * ALDV + c4] =
                make_uint4(f2tf32(vv.x), f2tf32(vv.y), f2tf32(vv.z), f2tf32(vv.w));
        }
        __syncthreads();

        // --- S = (Q*qscale) @ K^T  (exp2 domain) ---
        float s[8][4];
        #pragma unroll
        for (int nt = 0; nt < 8; nt++)
            #pragma unroll
            for (int c = 0; c < 4; c++) s[nt][c] = 0.0f;

        #pragma unroll
        for (int k8 = 0; k8 < 8; k8++) {
            #pragma unroll
            for (int nt = 0; nt < 8; nt++) {
                uint32_t b0 = Ks[(nt * 8 + g) * ALDK + k8 * 8 + tig    ];
                uint32_t b1 = Ks[(nt * 8 + g) * ALDK + k8 * 8 + tig + 4];
                mma_tf32(s[nt][0], s[nt][1], s[nt][2], s[nt][3],
                         qf[k8][0], qf[k8][1], qf[k8][2], qf[k8][3], b0, b1);
            }
        }

        // --- causal mask (only diagonal-adjacent tiles) ---
        if (kt >= 2 * qtile) {
            int qr0 = q0 + wrow + g;
            int qr1 = qr0 + 8;
            #pragma unroll
            for (int nt = 0; nt < 8; nt++) {
                int c = kt * AKT + nt * 8 + tig * 2;
                if (c     > qr0) s[nt][0] = -1e30f;
                if (c + 1 > qr0) s[nt][1] = -1e30f;
                if (c     > qr1) s[nt][2] = -1e30f;
                if (c + 1 > qr1) s[nt][3] = -1e30f;
            }
        }

        // --- online softmax, exp2 domain (rows g and g+8; quad shuffle) ---
        float mt0 = -1e30f, mt1 = -1e30f;
        #pragma unroll
        for (int nt = 0; nt < 8; nt++) {
            mt0 = fmaxf(mt0, fmaxf(s[nt][0], s[nt][1]));
            mt1 = fmaxf(mt1, fmaxf(s[nt][2], s[nt][3]));
        }
        #pragma unroll
        for (int off = 1; off <= 2; off <<= 1) {
            mt0 = fmaxf(mt0, __shfl_xor_sync(0xffffffffu, mt0, off));
            mt1 = fmaxf(mt1, __shfl_xor_sync(0xffffffffu, mt1, off));
        }

        float mn0 = fmaxf(m0, mt0);
        float mn1 = fmaxf(m1, mt1);
        float alpha0 = exp2f(m0 - mn0);
        float alpha1 = exp2f(m1 - mn1);
        m0 = mn0; m1 = mn1;

        float ps0 = 0.0f, ps1 = 0.0f;
        #pragma unroll
        for (int nt = 0; nt < 8; nt++) {
            s[nt][0] = exp2f(s[nt][0] - mn0);
            s[nt][1] = exp2f(s[nt][1] - mn0);
            s[nt][2] = exp2f(s[nt][2] - mn1);
            s[nt][3] = exp2f(s[nt][3] - mn1);
            ps0 += s[nt][0] + s[nt][1];
            ps1 += s[nt][2] + s[nt][3];
        }
        #pragma unroll
        for (int off = 1; off <= 2; off <<= 1) {
            ps0 += __shfl_xor_sync(0xffffffffu, ps0, off);
            ps1 += __shfl_xor_sync(0xffffffffu, ps1, off);
        }
        l0 = l0 * alpha0 + ps0;
        l1 = l1 * alpha1 + ps1;

        #pragma unroll
        for (int nt = 0; nt < 8; nt++) {
            o[nt][0] *= alpha0; o[nt][1] *= alpha0;
            o[nt][2] *= alpha1; o[nt][3] *= alpha1;
        }

        // --- write P to smem (tf32 bits), re-enter as A operand ---
        {
            uint32_t* pr0 = &Ps[(wrow + g    ) * ALDK];
            uint32_t* pr1 = &Ps[(wrow + g + 8) * ALDK];
            #pragma unroll
            for (int nt = 0; nt < 8; nt++) {
                int c = nt * 8 + tig * 2;
                pr0[c    ] = f2tf32(s[nt][0]);
                pr0[c + 1] = f2tf32(s[nt][1]);
                pr1[c    ] = f2tf32(s[nt][2]);
                pr1[c + 1] = f2tf32(s[nt][3]);
            }
        }
        __syncwarp();   // own-warp cross-lane STS->LDS visibility

        // --- O += P @ V  (B-frags straight from natural-layout Vs) ---
        #pragma unroll
        for (int k8 = 0; k8 < 8; k8++) {
            const int kb = k8 * 8;
            uint32_t af0 = Ps[(wrow + g    ) * ALDK + kb + tig    ];
            uint32_t af1 = Ps[(wrow + g + 8) * ALDK + kb + tig    ];
            uint32_t af2 = Ps[(wrow + g    ) * ALDK + kb + tig + 4];
            uint32_t af3 = Ps[(wrow + g + 8) * ALDK + kb + tig + 4];
            #pragma unroll
            for (int nt = 0; nt < 8; nt++) {
                uint32_t b0 = Vs[(kb + tig    ) * ALDV + nt * 8 + g];
                uint32_t b1 = Vs[(kb + tig + 4) * ALDV + nt * 8 + g];
                mma_tf32(o[nt][0], o[nt][1], o[nt][2], o[nt][3],
                         af0, af1, af2, af3, b0, b1);
            }
        }
        __syncthreads();   // protect Ks/Vs before next tile's staging
    }

    // --- finalize ---
    float inv0 = 1.0f / l0;
    float inv1 = 1.0f / l1;
    float* Or0 = O + base + (size_t)(q0 + wrow + g) * D_MODEL;
    float* Or1 = Or0 + 8 * D_MODEL;
    #pragma unroll
    for (int nt = 0; nt < 8; nt++) {
        int c = nt * 8 + tig * 2;
        *(float2*)&Or0[c] = make_float2(o[nt][0] * inv0, o[nt][1] * inv0);
        *(float2*)&Or1[c] = make_float2(o[nt][2] * inv1, o[nt][3] * inv1);
    }
}

// ---------------------------------------------------------------------------
// Launch
// ---------------------------------------------------------------------------
extern "C" void kernel_launch(void* const* d_in, const int* in_sizes, int n_in,
                              void* d_out, int out_size)
{
    const float* x  = (const float*)d_in[0];
    const float* Wq = (const float*)d_in[1];
    const float* Wk = (const float*)d_in[2];
    const float* Wv = (const float*)d_in[3];
    const float* Wo = (const float*)d_in[4];
    float* out = (float*)d_out;

    float *q, *k, *v, *o;
    cudaGetSymbolAddress((void**)&q, g_q);
    cudaGetSymbolAddress((void**)&k, g_k);
    cudaGetSymbolAddress((void**)&v, g_v);
    cudaGetSymbolAddress((void**)&o, g_o);

    cudaFuncSetAttribute(attn_mma_kernel,
                         cudaFuncAttributeMaxDynamicSharedMemorySize,
                         ATTN_SMEM_BYTES);

    dim3 blk(256);

    // Fused QKV: one work-conserving launch (768 CTAs)
    dim3 qkv_grid(3 * (D_MODEL / GBN), MTOT / GBM);   // (24, 32)
    gemm_tf32_multi<<<qkv_grid, blk>>>(x, Wq, Wk, Wv, q, k, v,
                                       MTOT, D_MODEL, D_MODEL);

    dim3 attn_grid(SEQ / AQT, NUM_HEADS, BATCH);      // (16, 16, 2)
    attn_mma_kernel<<<attn_grid, blk, ATTN_SMEM_BYTES>>>(q, k, v, o);

    // Output projection
    dim3 o_grid(D_MODEL / GBN, MTOT / GBM);           // (8, 32)
    gemm_tf32_multi<<<o_grid, blk>>>(o, Wo, Wo, Wo, out, out, out,
                                     MTOT, D_MODEL, D_MODEL);
}

// round 15
// speedup vs baseline: 1.3442x; 1.0706x over previous
#include <cuda_runtime.h>
#include <cstdint>

#define D_MODEL   1024
#define NUM_HEADS 16
#define HEAD_DIM  64
#define BATCH     2
#define SEQ       2048
#define MTOT      (BATCH * SEQ)   /* 4096 rows */

// ---------------------------------------------------------------------------
// Scratch (device globals; no allocation allowed)
// ---------------------------------------------------------------------------
__device__ float g_q[MTOT * D_MODEL];
__device__ float g_k[MTOT * D_MODEL];
__device__ float g_v[MTOT * D_MODEL];
__device__ float g_o[MTOT * D_MODEL];
__device__ float g_xr[MTOT * D_MODEL];            /* tf32-rounded x   */
__device__ float g_wr[4 * D_MODEL * D_MODEL];     /* tf32-rounded W's */

__device__ __forceinline__ uint32_t f2tf32(float f) {
    uint32_t r;
    asm("cvt.rna.tf32.f32 %0, %1;" : "=r"(r) : "f"(f));
    return r;
}
__device__ __forceinline__ float rtf(float f) { return __uint_as_float(f2tf32(f)); }

__device__ __forceinline__ uint32_t smem_u32(const void* p) {
    uint32_t a;
    asm("{ .reg .u64 t; cvta.to.shared.u64 t, %1; cvt.u32.u64 %0, t; }"
        : "=r"(a) : "l"(p));
    return a;
}
__device__ __forceinline__ void cp16(uint32_t dst, const void* src) {
    asm volatile("cp.async.cg.shared.global [%0], [%1], 16;" :: "r"(dst), "l"(src));
}
#define CP_COMMIT() asm volatile("cp.async.commit_group;")
#define CP_WAIT(n)  asm volatile("cp.async.wait_group %0;" :: "n"(n))

__device__ __forceinline__ void mma_tf32(
    float& c0, float& c1, float& c2, float& c3,
    uint32_t a0, uint32_t a1, uint32_t a2, uint32_t a3,
    uint32_t b0, uint32_t b1)
{
    asm volatile(
        "mma.sync.aligned.m16n8k8.row.col.f32.tf32.tf32.f32 "
        "{%0,%1,%2,%3}, {%4,%5,%6,%7}, {%8,%9}, {%0,%1,%2,%3};"
        : "+f"(c0), "+f"(c1), "+f"(c2), "+f"(c3)
        : "r"(a0), "r"(a1), "r"(a2), "r"(a3), "r"(b0), "r"(b1));
}

// ---------------------------------------------------------------------------
// Pre-round pass: x and the four weight matrices -> tf32-exact fp32 scratch.
// ---------------------------------------------------------------------------
#define N4_X (MTOT * D_MODEL / 4)       /* 1048576 */
#define N4_W (D_MODEL * D_MODEL / 4)    /* 262144  */

__global__ __launch_bounds__(256) void round_inputs(
    const float4* __restrict__ x,
    const float4* __restrict__ wq, const float4* __restrict__ wk,
    const float4* __restrict__ wv, const float4* __restrict__ wo,
    float4* __restrict__ xr, float4* __restrict__ wr)
{
    int i = blockIdx.x * 256 + threadIdx.x;
    const float4* src;
    float4* dst;
    int off;
    if (i < N4_X) {
        src = x; dst = xr; off = i;
    } else {
        int j = i - N4_X;
        int w = j / N4_W;
        off   = j - w * N4_W;
        src = (w == 0) ? wq : (w == 1) ? wk : (w == 2) ? wv : wo;
        dst = wr + (size_t)w * N4_W;
    }
    float4 v = src[off];
    dst[off] = make_float4(rtf(v.x), rtf(v.y), rtf(v.z), rtf(v.w));
}

// ---------------------------------------------------------------------------
// TF32 tensor-core GEMM:  C[M,N] = A[M,K] @ B[N,K]^T  (row-major, K contig)
// Inputs are tf32-exact fp32 -> staged raw via cp.async (no cvt in loop).
// Double-buffered: issue next tile's LDGSTS, wait previous, compute. One
// barrier pair per iter, ZERO prefetch registers.
// Multi-matrix: blockIdx.x >> 3 selects (B, C) pair -> QKV in one launch.
// ---------------------------------------------------------------------------
#define GBM 128
#define GBN 128
#define GBK 32
#define LDS_K 36   /* padded smem stride (words): 32 + 4; row pitch 144B = 9*16 */

#define GEMM_BUF_WORDS (2 * GBM * LDS_K)            /* As+Bs per stage */
#define GEMM_SMEM_BYTES (2 * GEMM_BUF_WORDS * 4)    /* 73728 B */

__device__ __forceinline__ void gemm_cp(
    const float* __restrict__ A, const float* __restrict__ B,
    int m0, int n0, int K, int k0, int tid, uint32_t sA, uint32_t sB)
{
    #pragma unroll
    for (int i = 0; i < 4; i++) {
        int e  = tid + i * 256;
        int r  = e >> 3;
        int c4 = (e & 7) * 4;
        cp16(sA + (r * LDS_K + c4) * 4, &A[(size_t)(m0 + r) * K + k0 + c4]);
        cp16(sB + (r * LDS_K + c4) * 4, &B[(size_t)(n0 + r) * K + k0 + c4]);
    }
}

__global__ __launch_bounds__(256, 2) void gemm_tf32_multi(
    const float* __restrict__ A,
    const float* __restrict__ B0, const float* __restrict__ B1,
    const float* __restrict__ B2,
    float* __restrict__ C0, float* __restrict__ C1, float* __restrict__ C2,
    int M, int N, int K, int round_c)
{
    extern __shared__ uint32_t gsm[];
    const uint32_t sb = smem_u32(gsm);

    const int w = blockIdx.x >> 3;
    const float* B = (w == 0) ? B0 : (w == 1) ? B1 : B2;
    float*       C = (w == 0) ? C0 : (w == 1) ? C1 : C2;

    const int tid     = threadIdx.x;
    const int lane    = tid & 31;
    const int warp    = tid >> 5;
    const int groupID = lane >> 2;
    const int tig     = lane & 3;

    const int m0 = blockIdx.y * GBM;
    const int n0 = (blockIdx.x & 7) * GBN;
    const int m_warp = (warp >> 1) * 32;
    const int n_warp = (warp & 1) * 64;

    float acc[2][8][4];
    #pragma unroll
    for (int mt = 0; mt < 2; mt++)
        #pragma unroll
        for (int nt = 0; nt < 8; nt++)
            #pragma unroll
            for (int c = 0; c < 4; c++) acc[mt][nt][c] = 0.0f;

    gemm_cp(A, B, m0, n0, K, 0, tid, sb, sb + GBM * LDS_K * 4);
    CP_COMMIT();

    const int nk = K / GBK;
    for (int kt = 0; kt < nk; kt++) {
        if (kt + 1 < nk) {
            uint32_t s = sb + ((kt + 1) & 1) * GEMM_BUF_WORDS * 4;
            gemm_cp(A, B, m0, n0, K, (kt + 1) * GBK, tid, s, s + GBM * LDS_K * 4);
            CP_COMMIT();
            CP_WAIT(1);
        } else {
            CP_WAIT(0);
        }
        __syncthreads();

        const uint32_t* cA = gsm + (kt & 1) * GEMM_BUF_WORDS;
        const uint32_t* cB = cA + GBM * LDS_K;

        #pragma unroll
        for (int kk8 = 0; kk8 < GBK / 8; kk8++) {
            const int kb = kk8 * 8;

            uint32_t a[2][4];
            #pragma unroll
            for (int mt = 0; mt < 2; mt++) {
                int r = m_warp + mt * 16 + groupID;
                a[mt][0] = cA[(r    ) * LDS_K + kb + tig    ];
                a[mt][1] = cA[(r + 8) * LDS_K + kb + tig    ];
                a[mt][2] = cA[(r    ) * LDS_K + kb + tig + 4];
                a[mt][3] = cA[(r + 8) * LDS_K + kb + tig + 4];
            }

            uint32_t b[8][2];
            #pragma unroll
            for (int nt = 0; nt < 8; nt++) {
                int r = n_warp + nt * 8 + groupID;
                b[nt][0] = cB[r * LDS_K + kb + tig    ];
                b[nt][1] = cB[r * LDS_K + kb + tig + 4];
            }

            #pragma unroll
            for (int mt = 0; mt < 2; mt++)
                #pragma unroll
                for (int nt = 0; nt < 8; nt++)
                    mma_tf32(acc[mt][nt][0], acc[mt][nt][1],
                             acc[mt][nt][2], acc[mt][nt][3],
                             a[mt][0], a[mt][1], a[mt][2], a[mt][3],
                             b[nt][0], b[nt][1]);
        }
        __syncthreads();
    }

    #pragma unroll
    for (int mt = 0; mt < 2; mt++) {
        int row = m0 + m_warp + mt * 16 + groupID;
        #pragma unroll
        for (int nt = 0; nt < 8; nt++) {
            int col = n0 + n_warp + nt * 8 + tig * 2;
            float v0 = acc[mt][nt][0], v1 = acc[mt][nt][1];
            float v2 = acc[mt][nt][2], v3 = acc[mt][nt][3];
            if (round_c) { v0 = rtf(v0); v1 = rtf(v1); v2 = rtf(v2); v3 = rtf(v3); }
            *(float2*)&C[(size_t)(row    ) * N + col] = make_float2(v0, v1);
            *(float2*)&C[(size_t)(row + 8) * N + col] = make_float2(v2, v3);
        }
    }
}

// ---------------------------------------------------------------------------
// Tensor-core flash attention (tf32 mma, fp32 softmax/accumulators).
// CTA = 128 q-rows x (head, batch). 8 warps; warp owns 16 rows.
// K/V inputs are tf32-exact -> cp.async double-buffered staging: next KV
// tile's LDGSTS fully overlaps QK mma + softmax + PV mma of the current one.
// K [kv][d] stride 68 (QK B-frags banks 4g+tig); V natural [kv][d] stride 72
// (PV B-frags banks 8*tig+g). exp2-domain softmax.
// ---------------------------------------------------------------------------
#define AQT   128
#define AKT   64
#define ALDK  68   /* K/P padded word stride; row pitch 272B = 17*16 */
#define ALDV  72   /* V padded word stride;  row pitch 288B = 18*16 */

#define SKW      (AKT * ALDK)              /* 4352 words */
#define SVW      (AKT * ALDV)              /* 4608 words */
#define STAGE_W  (SKW + SVW)               /* 8960 words */
#define ATTN_SMEM_WORDS (2 * STAGE_W + AQT * ALDK)
#define ATTN_SMEM_BYTES (ATTN_SMEM_WORDS * 4)   /* 106496 B */

__device__ __forceinline__ void attn_cp(
    const float* __restrict__ K, const float* __restrict__ V,
    size_t base, int kt, int tid, uint32_t sK, uint32_t sV)
{
    #pragma unroll
    for (int i = 0; i < 4; i++) {
        int e  = tid + i * 256;
        int r  = e >> 4;
        int c4 = (e & 15) * 4;
        size_t g = base + (size_t)(kt * AKT + r) * D_MODEL + c4;
        cp16(sK + (r * ALDK + c4) * 4, &K[g]);
        cp16(sV + (r * ALDV + c4) * 4, &V[g]);
    }
}

__global__ __launch_bounds__(256, 2) void attn_mma_kernel(
    const float* __restrict__ Q, const float* __restrict__ K,
    const float* __restrict__ V, float* __restrict__ O)
{
    extern __shared__ uint32_t sm[];
    const uint32_t sb = smem_u32(sm);
    uint32_t* Ps = sm + 2 * STAGE_W;      // [128][68] q x kv

    const int qtile = (int)gridDim.x - 1 - (int)blockIdx.x;  // heavy tiles first
    const int h    = blockIdx.y;
    const int b    = blockIdx.z;
    const int tid  = threadIdx.x;
    const int lane = tid & 31;
    const int warp = tid >> 5;
    const int g    = lane >> 2;
    const int tig  = lane & 3;
    const int wrow = warp * 16;

    const size_t base = (size_t)b * SEQ * D_MODEL + (size_t)h * HEAD_DIM;
    const int q0 = qtile * AQT;
    const int ktmax = 2 * qtile + 1;

    // kick off first KV tile, then load Q frags under it
    attn_cp(K, V, base, 0, tid, sb, sb + SKW * 4);
    CP_COMMIT();

    // Q fragments, pre-scaled by log2(e)/sqrt(HEAD_DIM)
    const float qscale = 0.125f * 1.44269504088896340736f;
    uint32_t qf[8][4];
    {
        const float* Qr0 = Q + base + (size_t)(q0 + wrow + g) * D_MODEL;
        const float* Qr1 = Qr0 + 8 * D_MODEL;
        #pragma unroll
        for (int k8 = 0; k8 < 8; k8++) {
            qf[k8][0] = f2tf32(qscale * Qr0[k8 * 8 + tig]);
            qf[k8][1] = f2tf32(qscale * Qr1[k8 * 8 + tig]);
            qf[k8][2] = f2tf32(qscale * Qr0[k8 * 8 + tig + 4]);
            qf[k8][3] = f2tf32(qscale * Qr1[k8 * 8 + tig + 4]);
        }
    }

    float o[8][4];
    #pragma unroll
    for (int nt = 0; nt < 8; nt++)
        #pragma unroll
        for (int c = 0; c < 4; c++) o[nt][c] = 0.0f;

    float m0 = -1e30f, m1 = -1e30f, l0 = 0.0f, l1 = 0.0f;

    for (int kt = 0; kt <= ktmax; kt++) {
        // issue next tile's loads; they fly under this tile's full compute
        if (kt < ktmax) {
            uint32_t s = sb + ((kt + 1) & 1) * STAGE_W * 4;
            attn_cp(K, V, base, kt + 1, tid, s, s + SKW * 4);
            CP_COMMIT();
            CP_WAIT(1);
        } else {
            CP_WAIT(0);
        }
        __syncthreads();

        const uint32_t* Ks = sm + (kt & 1) * STAGE_W;
        const uint32_t* Vs = Ks + SKW;

        // --- S = (Q*qscale) @ K^T  (exp2 domain) ---
        float s[8][4];
        #pragma unroll
        for (int nt = 0; nt < 8; nt++)
            #pragma unroll
            for (int c = 0; c < 4; c++) s[nt][c] = 0.0f;

        #pragma unroll
        for (int k8 = 0; k8 < 8; k8++) {
            #pragma unroll
            for (int nt = 0; nt < 8; nt++) {
                uint32_t b0 = Ks[(nt * 8 + g) * ALDK + k8 * 8 + tig    ];
                uint32_t b1 = Ks[(nt * 8 + g) * ALDK + k8 * 8 + tig + 4];
                mma_tf32(s[nt][0], s[nt][1], s[nt][2], s[nt][3],
                         qf[k8][0], qf[k8][1], qf[k8][2], qf[k8][3], b0, b1);
            }
        }

        // --- causal mask (only diagonal-adjacent tiles) ---
        if (kt >= 2 * qtile) {
            int qr0 = q0 + wrow + g;
            int qr1 = qr0 + 8;
            #pragma unroll
            for (int nt = 0; nt < 8; nt++) {
                int c = kt * AKT + nt * 8 + tig * 2;
                if (c     > qr0) s[nt][0] = -1e30f;
                if (c + 1 > qr0) s[nt][1] = -1e30f;
                if (c     > qr1) s[nt][2] = -1e30f;
                if (c + 1 > qr1) s[nt][3] = -1e30f;
            }
        }

        // --- online softmax, exp2 domain (rows g and g+8; quad shuffle) ---
        float mt0 = -1e30f, mt1 = -1e30f;
        #pragma unroll
        for (int nt = 0; nt < 8; nt++) {
            mt0 = fmaxf(mt0, fmaxf(s[nt][0], s[nt][1]));
            mt1 = fmaxf(mt1, fmaxf(s[nt][2], s[nt][3]));
        }
        #pragma unroll
        for (int off = 1; off <= 2; off <<= 1) {
            mt0 = fmaxf(mt0, __shfl_xor_sync(0xffffffffu, mt0, off));
            mt1 = fmaxf(mt1, __shfl_xor_sync(0xffffffffu, mt1, off));
        }

        float mn0 = fmaxf(m0, mt0);
        float mn1 = fmaxf(m1, mt1);
        float alpha0 = exp2f(m0 - mn0);
        float alpha1 = exp2f(m1 - mn1);
        m0 = mn0; m1 = mn1;

        float ps0 = 0.0f, ps1 = 0.0f;
        #pragma unroll
        for (int nt = 0; nt < 8; nt++) {
            s[nt][0] = exp2f(s[nt][0] - mn0);
            s[nt][1] = exp2f(s[nt][1] - mn0);
            s[nt][2] = exp2f(s[nt][2] - mn1);
            s[nt][3] = exp2f(s[nt][3] - mn1);
            ps0 += s[nt][0] + s[nt][1];
            ps1 += s[nt][2] + s[nt][3];
        }
        #pragma unroll
        for (int off = 1; off <= 2; off <<= 1) {
            ps0 += __shfl_xor_sync(0xffffffffu, ps0, off);
            ps1 += __shfl_xor_sync(0xffffffffu, ps1, off);
        }
        l0 = l0 * alpha0 + ps0;
        l1 = l1 * alpha1 + ps1;

        #pragma unroll
        for (int nt = 0; nt < 8; nt++) {
            o[nt][0] *= alpha0; o[nt][1] *= alpha0;
            o[nt][2] *= alpha1; o[nt][3] *= alpha1;
        }

        // --- write P to smem (tf32 bits), re-enter as A operand ---
        {
            uint32_t* pr0 = &Ps[(wrow + g    ) * ALDK];
            uint32_t* pr1 = &Ps[(wrow + g + 8) * ALDK];
            #pragma unroll
            for (int nt = 0; nt < 8; nt++) {
                int c = nt * 8 + tig * 2;
                pr0[c    ] = f2tf32(s[nt][0]);
                pr0[c + 1] = f2tf32(s[nt][1]);
                pr1[c    ] = f2tf32(s[nt][2]);
                pr1[c + 1] = f2tf32(s[nt][3]);
            }
        }
        __syncwarp();   // own-warp cross-lane STS->LDS visibility

        // --- O += P @ V  (B-frags straight from natural-layout Vs) ---
        #pragma unroll
        for (int k8 = 0; k8 < 8; k8++) {
            const int kb = k8 * 8;
            uint32_t af0 = Ps[(wrow + g    ) * ALDK + kb + tig    ];
            uint32_t af1 = Ps[(wrow + g + 8) * ALDK + kb + tig    ];
            uint32_t af2 = Ps[(wrow + g    ) * ALDK + kb + tig + 4];
            uint32_t af3 = Ps[(wrow + g + 8) * ALDK + kb + tig + 4];
            #pragma unroll
            for (int nt = 0; nt < 8; nt++) {
                uint32_t b0 = Vs[(kb + tig    ) * ALDV + nt * 8 + g];
                uint32_t b1 = Vs[(kb + tig + 4) * ALDV + nt * 8 + g];
                mma_tf32(o[nt][0], o[nt][1], o[nt][2], o[nt][3],
                         af0, af1, af2, af3, b0, b1);
            }
        }
        __syncthreads();   // compute done before next iter's cp overwrites
    }

    // --- finalize (tf32-rounded so the O-projection can cp.async raw) ---
    float inv0 = 1.0f / l0;
    float inv1 = 1.0f / l1;
    float* Or0 = O + base + (size_t)(q0 + wrow + g) * D_MODEL;
    float* Or1 = Or0 + 8 * D_MODEL;
    #pragma unroll
    for (int nt = 0; nt < 8; nt++) {
        int c = nt * 8 + tig * 2;
        *(float2*)&Or0[c] = make_float2(rtf(o[nt][0] * inv0), rtf(o[nt][1] * inv0));
        *(float2*)&Or1[c] = make_float2(rtf(o[nt][2] * inv1), rtf(o[nt][3] * inv1));
    }
}

// ---------------------------------------------------------------------------
// Launch
// ---------------------------------------------------------------------------
extern "C" void kernel_launch(void* const* d_in, const int* in_sizes, int n_in,
                              void* d_out, int out_size)
{
    const float* x  = (const float*)d_in[0];
    const float* Wq = (const float*)d_in[1];
    const float* Wk = (const float*)d_in[2];
    const float* Wv = (const float*)d_in[3];
    const float* Wo = (const float*)d_in[4];
    float* out = (float*)d_out;

    float *q, *k, *v, *o, *xr, *wr;
    cudaGetSymbolAddress((void**)&q,  g_q);
    cudaGetSymbolAddress((void**)&k,  g_k);
    cudaGetSymbolAddress((void**)&v,  g_v);
    cudaGetSymbolAddress((void**)&o,  g_o);
    cudaGetSymbolAddress((void**)&xr, g_xr);
    cudaGetSymbolAddress((void**)&wr, g_wr);

    cudaFuncSetAttribute(gemm_tf32_multi,
                         cudaFuncAttributeMaxDynamicSharedMemorySize,
                         GEMM_SMEM_BYTES);
    cudaFuncSetAttribute(attn_mma_kernel,
                         cudaFuncAttributeMaxDynamicSharedMemorySize,
                         ATTN_SMEM_BYTES);

    dim3 blk(256);

    // 0) pre-round x + weights to tf32-exact fp32
    int n4 = N4_X + 4 * N4_W;
    round_inputs<<<n4 / 256, blk>>>(
        (const float4*)x, (const float4*)Wq, (const float4*)Wk,
        (const float4*)Wv, (const float4*)Wo, (float4*)xr, (float4*)wr);

    const size_t WSZ = (size_t)D_MODEL * D_MODEL;

    // 1) fused QKV projection (rounded outputs for attn's cp.async)
    dim3 qkv_grid(3 * (D_MODEL / GBN), MTOT / GBM);   // (24, 32)
    gemm_tf32_multi<<<qkv_grid, blk, GEMM_SMEM_BYTES>>>(
        xr, wr, wr + WSZ, wr + 2 * WSZ, q, k, v, MTOT, D_MODEL, D_MODEL, 1);

    // 2) attention
    dim3 attn_grid(SEQ / AQT, NUM_HEADS, BATCH);      // (16, 16, 2)
    attn_mma_kernel<<<attn_grid, blk, ATTN_SMEM_BYTES>>>(q, k, v, o);

    // 3) output projection (plain fp32 out)
    dim3 o_grid(D_MODEL / GBN, MTOT / GBM);           // (8, 32)
    gemm_tf32_multi<<<o_grid, blk, GEMM_SMEM_BYTES>>>(
        o, wr + 3 * WSZ, wr + 3 * WSZ, wr + 3 * WSZ, out, out, out,
        MTOT, D_MODEL, D_MODEL, 0);
}

// round 16
// speedup vs baseline: 1.3705x; 1.0195x over previous
#include <cuda_runtime.h>
#include <cstdint>

#define D_MODEL   1024
#define NUM_HEADS 16
#define HEAD_DIM  64
#define BATCH     2
#define SEQ       2048
#define MTOT      (BATCH * SEQ)   /* 4096 rows */

// ---------------------------------------------------------------------------
// Scratch (device globals; no allocation allowed)
// ---------------------------------------------------------------------------
__device__ float g_q[MTOT * D_MODEL];
__device__ float g_k[MTOT * D_MODEL];
__device__ float g_v[MTOT * D_MODEL];
__device__ float g_o[MTOT * D_MODEL];
__device__ float g_xr[MTOT * D_MODEL];            /* tf32-rounded x   */
__device__ float g_wr[4 * D_MODEL * D_MODEL];     /* tf32-rounded W's */

__device__ __forceinline__ uint32_t f2tf32(float f) {
    uint32_t r;
    asm("cvt.rna.tf32.f32 %0, %1;" : "=r"(r) : "f"(f));
    return r;
}
__device__ __forceinline__ float rtf(float f) { return __uint_as_float(f2tf32(f)); }

__device__ __forceinline__ uint32_t smem_u32(const void* p) {
    uint32_t a;
    asm("{ .reg .u64 t; cvta.to.shared.u64 t, %1; cvt.u32.u64 %0, t; }"
        : "=r"(a) : "l"(p));
    return a;
}
__device__ __forceinline__ void cp16(uint32_t dst, const void* src) {
    asm volatile("cp.async.cg.shared.global [%0], [%1], 16;" :: "r"(dst), "l"(src));
}
#define CP_COMMIT() asm volatile("cp.async.commit_group;")
#define CP_WAIT(n)  asm volatile("cp.async.wait_group %0;" :: "n"(n))

__device__ __forceinline__ void mma_tf32(
    float& c0, float& c1, float& c2, float& c3,
    uint32_t a0, uint32_t a1, uint32_t a2, uint32_t a3,
    uint32_t b0, uint32_t b1)
{
    asm volatile(
        "mma.sync.aligned.m16n8k8.row.col.f32.tf32.tf32.f32 "
        "{%0,%1,%2,%3}, {%4,%5,%6,%7}, {%8,%9}, {%0,%1,%2,%3};"
        : "+f"(c0), "+f"(c1), "+f"(c2), "+f"(c3)
        : "r"(a0), "r"(a1), "r"(a2), "r"(a3), "r"(b0), "r"(b1));
}

// ---------------------------------------------------------------------------
// Pre-round pass: x and the four weight matrices -> tf32-exact fp32 scratch.
// ---------------------------------------------------------------------------
#define N4_X (MTOT * D_MODEL / 4)       /* 1048576 */
#define N4_W (D_MODEL * D_MODEL / 4)    /* 262144  */

__global__ __launch_bounds__(256) void round_inputs(
    const float4* __restrict__ x,
    const float4* __restrict__ wq, const float4* __restrict__ wk,
    const float4* __restrict__ wv, const float4* __restrict__ wo,
    float4* __restrict__ xr, float4* __restrict__ wr)
{
    int i = blockIdx.x * 256 + threadIdx.x;
    const float4* src;
    float4* dst;
    int off;
    if (i < N4_X) {
        src = x; dst = xr; off = i;
    } else {
        int j = i - N4_X;
        int w = j / N4_W;
        off   = j - w * N4_W;
        src = (w == 0) ? wq : (w == 1) ? wk : (w == 2) ? wv : wo;
        dst = wr + (size_t)w * N4_W;
    }
    float4 v = src[off];
    dst[off] = make_float4(rtf(v.x), rtf(v.y), rtf(v.z), rtf(v.w));
}

// ---------------------------------------------------------------------------
// TF32 tensor-core GEMM:  C[M,N] = A[M,K] @ B[N,K]^T  (row-major, K contig)
// 128x128 CTA tile, BK=32, **128 threads: 4 warps, 2x2, warp tile 64x64**.
// Per kk8 per warp: 32 LDS.32 feed 32 HMMAs (128 B/mma; was 192) -> smem
// crossbar pressure cut 1.5x. Inputs tf32-exact, staged raw via cp.async,
// double-buffered. Multi-matrix: blockIdx.x >> 3 selects (B, C) pair.
// ---------------------------------------------------------------------------
#define GBM 128
#define GBN 128
#define GBK 32
#define LDS_K 36   /* padded smem stride (words): 32 + 4; row pitch 144B */

#define GEMM_BUF_WORDS (2 * GBM * LDS_K)            /* As+Bs per stage */
#define GEMM_SMEM_BYTES (2 * GEMM_BUF_WORDS * 4)    /* 73728 B */

__device__ __forceinline__ void gemm_cp(
    const float* __restrict__ A, const float* __restrict__ B,
    int m0, int n0, int K, int k0, int tid, uint32_t sA, uint32_t sB)
{
    #pragma unroll
    for (int i = 0; i < 8; i++) {
        int e  = tid + i * 128;        // 0..1023 float4-slots
        int r  = e >> 3;
        int c4 = (e & 7) * 4;
        cp16(sA + (r * LDS_K + c4) * 4, &A[(size_t)(m0 + r) * K + k0 + c4]);
        cp16(sB + (r * LDS_K + c4) * 4, &B[(size_t)(n0 + r) * K + k0 + c4]);
    }
}

__global__ __launch_bounds__(128, 2) void gemm_tf32_multi(
    const float* __restrict__ A,
    const float* __restrict__ B0, const float* __restrict__ B1,
    const float* __restrict__ B2,
    float* __restrict__ C0, float* __restrict__ C1, float* __restrict__ C2,
    int M, int N, int K, int round_c)
{
    extern __shared__ uint32_t gsm[];
    const uint32_t sb = smem_u32(gsm);

    const int w = blockIdx.x >> 3;
    const float* B = (w == 0) ? B0 : (w == 1) ? B1 : B2;
    float*       C = (w == 0) ? C0 : (w == 1) ? C1 : C2;

    const int tid     = threadIdx.x;
    const int lane    = tid & 31;
    const int warp    = tid >> 5;
    const int groupID = lane >> 2;
    const int tig     = lane & 3;

    const int m0 = blockIdx.y * GBM;
    const int n0 = (blockIdx.x & 7) * GBN;
    const int m_warp = (warp >> 1) * 64;   // 0,64
    const int n_warp = (warp & 1) * 64;    // 0,64

    float acc[4][8][4];
    #pragma unroll
    for (int mt = 0; mt < 4; mt++)
        #pragma unroll
        for (int nt = 0; nt < 8; nt++)
            #pragma unroll
            for (int c = 0; c < 4; c++) acc[mt][nt][c] = 0.0f;

    gemm_cp(A, B, m0, n0, K, 0, tid, sb, sb + GBM * LDS_K * 4);
    CP_COMMIT();

    const int nk = K / GBK;
    for (int kt = 0; kt < nk; kt++) {
        if (kt + 1 < nk) {
            uint32_t s = sb + ((kt + 1) & 1) * GEMM_BUF_WORDS * 4;
            gemm_cp(A, B, m0, n0, K, (kt + 1) * GBK, tid, s, s + GBM * LDS_K * 4);
            CP_COMMIT();
            CP_WAIT(1);
        } else {
            CP_WAIT(0);
        }
        __syncthreads();

        const uint32_t* cA = gsm + (kt & 1) * GEMM_BUF_WORDS;
        const uint32_t* cB = cA + GBM * LDS_K;

        #pragma unroll
        for (int kk8 = 0; kk8 < GBK / 8; kk8++) {
            const int kb = kk8 * 8;

            uint32_t a[4][4];
            #pragma unroll
            for (int mt = 0; mt < 4; mt++) {
                int r = m_warp + mt * 16 + groupID;
                a[mt][0] = cA[(r    ) * LDS_K + kb + tig    ];
                a[mt][1] = cA[(r + 8) * LDS_K + kb + tig    ];
                a[mt][2] = cA[(r    ) * LDS_K + kb + tig + 4];
                a[mt][3] = cA[(r + 8) * LDS_K + kb + tig + 4];
            }

            uint32_t b[8][2];
            #pragma unroll
            for (int nt = 0; nt < 8; nt++) {
                int r = n_warp + nt * 8 + groupID;
                b[nt][0] = cB[r * LDS_K + kb + tig    ];
                b[nt][1] = cB[r * LDS_K + kb + tig + 4];
            }

            #pragma unroll
            for (int mt = 0; mt < 4; mt++)
                #pragma unroll
                for (int nt = 0; nt < 8; nt++)
                    mma_tf32(acc[mt][nt][0], acc[mt][nt][1],
                             acc[mt][nt][2], acc[mt][nt][3],
                             a[mt][0], a[mt][1], a[mt][2], a[mt][3],
                             b[nt][0], b[nt][1]);
        }
        __syncthreads();
    }

    #pragma unroll
    for (int mt = 0; mt < 4; mt++) {
        int row = m0 + m_warp + mt * 16 + groupID;
        #pragma unroll
        for (int nt = 0; nt < 8; nt++) {
            int col = n0 + n_warp + nt * 8 + tig * 2;
            float v0 = acc[mt][nt][0], v1 = acc[mt][nt][1];
            float v2 = acc[mt][nt][2], v3 = acc[mt][nt][3];
            if (round_c) { v0 = rtf(v0); v1 = rtf(v1); v2 = rtf(v2); v3 = rtf(v3); }
            *(float2*)&C[(size_t)(row    ) * N + col] = make_float2(v0, v1);
            *(float2*)&C[(size_t)(row + 8) * N + col] = make_float2(v2, v3);
        }
    }
}

// ---------------------------------------------------------------------------
// Tensor-core flash attention (tf32 mma, fp32 softmax/accumulators).
// (unchanged from R14 -- proven at ~160us)
// ---------------------------------------------------------------------------
#define AQT   128
#define AKT   64
#define ALDK  68
#define ALDV  72

#define SKW      (AKT * ALDK)
#define SVW      (AKT * ALDV)
#define STAGE_W  (SKW + SVW)
#define ATTN_SMEM_WORDS (2 * STAGE_W + AQT * ALDK)
#define ATTN_SMEM_BYTES (ATTN_SMEM_WORDS * 4)   /* 106496 B */

__device__ __forceinline__ void attn_cp(
    const float* __restrict__ K, const float* __restrict__ V,
    size_t base, int kt, int tid, uint32_t sK, uint32_t sV)
{
    #pragma unroll
    for (int i = 0; i < 4; i++) {
        int e  = tid + i * 256;
        int r  = e >> 4;
        int c4 = (e & 15) * 4;
        size_t g = base + (size_t)(kt * AKT + r) * D_MODEL + c4;
        cp16(sK + (r * ALDK + c4) * 4, &K[g]);
        cp16(sV + (r * ALDV + c4) * 4, &V[g]);
    }
}

__global__ __launch_bounds__(256, 2) void attn_mma_kernel(
    const float* __restrict__ Q, const float* __restrict__ K,
    const float* __restrict__ V, float* __restrict__ O)
{
    extern __shared__ uint32_t sm[];
    const uint32_t sb = smem_u32(sm);
    uint32_t* Ps = sm + 2 * STAGE_W;

    const int qtile = (int)gridDim.x - 1 - (int)blockIdx.x;
    const int h    = blockIdx.y;
    const int b    = blockIdx.z;
    const int tid  = threadIdx.x;
    const int lane = tid & 31;
    const int warp = tid >> 5;
    const int g    = lane >> 2;
    const int tig  = lane & 3;
    const int wrow = warp * 16;

    const size_t base = (size_t)b * SEQ * D_MODEL + (size_t)h * HEAD_DIM;
    const int q0 = qtile * AQT;
    const int ktmax = 2 * qtile + 1;

    attn_cp(K, V, base, 0, tid, sb, sb + SKW * 4);
    CP_COMMIT();

    const float qscale = 0.125f * 1.44269504088896340736f;
    uint32_t qf[8][4];
    {
        const float* Qr0 = Q + base + (size_t)(q0 + wrow + g) * D_MODEL;
        const float* Qr1 = Qr0 + 8 * D_MODEL;
        #pragma unroll
        for (int k8 = 0; k8 < 8; k8++) {
            qf[k8][0] = f2tf32(qscale * Qr0[k8 * 8 + tig]);
            qf[k8][1] = f2tf32(qscale * Qr1[k8 * 8 + tig]);
            qf[k8][2] = f2tf32(qscale * Qr0[k8 * 8 + tig + 4]);
            qf[k8][3] = f2tf32(qscale * Qr1[k8 * 8 + tig + 4]);
        }
    }

    float o[8][4];
    #pragma unroll
    for (int nt = 0; nt < 8; nt++)
        #pragma unroll
        for (int c = 0; c < 4; c++) o[nt][c] = 0.0f;

    float m0 = -1e30f, m1 = -1e30f, l0 = 0.0f, l1 = 0.0f;

    for (int kt = 0; kt <= ktmax; kt++) {
        if (kt < ktmax) {
            uint32_t s = sb + ((kt + 1) & 1) * STAGE_W * 4;
            attn_cp(K, V, base, kt + 1, tid, s, s + SKW * 4);
            CP_COMMIT();
            CP_WAIT(1);
        } else {
            CP_WAIT(0);
        }
        __syncthreads();

        const uint32_t* Ks = sm + (kt & 1) * STAGE_W;
        const uint32_t* Vs = Ks + SKW;

        float s[8][4];
        #pragma unroll
        for (int nt = 0; nt < 8; nt++)
            #pragma unroll
            for (int c = 0; c < 4; c++) s[nt][c] = 0.0f;

        #pragma unroll
        for (int k8 = 0; k8 < 8; k8++) {
            #pragma unroll
            for (int nt = 0; nt < 8; nt++) {
                uint32_t b0 = Ks[(nt * 8 + g) * ALDK + k8 * 8 + tig    ];
                uint32_t b1 = Ks[(nt * 8 + g) * ALDK + k8 * 8 + tig + 4];
                mma_tf32(s[nt][0], s[nt][1], s[nt][2], s[nt][3],
                         qf[k8][0], qf[k8][1], qf[k8][2], qf[k8][3], b0, b1);
            }
        }

        if (kt >= 2 * qtile) {
            int qr0 = q0 + wrow + g;
            int qr1 = qr0 + 8;
            #pragma unroll
            for (int nt = 0; nt < 8; nt++) {
                int c = kt * AKT + nt * 8 + tig * 2;
                if (c     > qr0) s[nt][0] = -1e30f;
                if (c + 1 > qr0) s[nt][1] = -1e30f;
                if (c     > qr1) s[nt][2] = -1e30f;
                if (c + 1 > qr1) s[nt][3] = -1e30f;
            }
        }

        float mt0 = -1e30f, mt1 = -1e30f;
        #pragma unroll
        for (int nt = 0; nt < 8; nt++) {
            mt0 = fmaxf(mt0, fmaxf(s[nt][0], s[nt][1]));
            mt1 = fmaxf(mt1, fmaxf(s[nt][2], s[nt][3]));
        }
        #pragma unroll
        for (int off = 1; off <= 2; off <<= 1) {
            mt0 = fmaxf(mt0, __shfl_xor_sync(0xffffffffu, mt0, off));
            mt1 = fmaxf(mt1, __shfl_xor_sync(0xffffffffu, mt1, off));
        }

        float mn0 = fmaxf(m0, mt0);
        float mn1 = fmaxf(m1, mt1);
        float alpha0 = exp2f(m0 - mn0);
        float alpha1 = exp2f(m1 - mn1);
        m0 = mn0; m1 = mn1;

        float ps0 = 0.0f, ps1 = 0.0f;
        #pragma unroll
        for (int nt = 0; nt < 8; nt++) {
            s[nt][0] = exp2f(s[nt][0] - mn0);
            s[nt][1] = exp2f(s[nt][1] - mn0);
            s[nt][2] = exp2f(s[nt][2] - mn1);
            s[nt][3] = exp2f(s[nt][3] - mn1);
            ps0 += s[nt][0] + s[nt][1];
            ps1 += s[nt][2] + s[nt][3];
        }
        #pragma unroll
        for (int off = 1; off <= 2; off <<= 1) {
            ps0 += __shfl_xor_sync(0xffffffffu, ps0, off);
            ps1 += __shfl_xor_sync(0xffffffffu, ps1, off);
        }
        l0 = l0 * alpha0 + ps0;
        l1 = l1 * alpha1 + ps1;

        #pragma unroll
        for (int nt = 0; nt < 8; nt++) {
            o[nt][0] *= alpha0; o[nt][1] *= alpha0;
            o[nt][2] *= alpha1; o[nt][3] *= alpha1;
        }

        {
            uint32_t* pr0 = &Ps[(wrow + g    ) * ALDK];
            uint32_t* pr1 = &Ps[(wrow + g + 8) * ALDK];
            #pragma unroll
            for (int nt = 0; nt < 8; nt++) {
                int c = nt * 8 + tig * 2;
                pr0[c    ] = f2tf32(s[nt][0]);
                pr0[c + 1] = f2tf32(s[nt][1]);
                pr1[c    ] = f2tf32(s[nt][2]);
                pr1[c + 1] = f2tf32(s[nt][3]);
            }
        }
        __syncwarp();

        #pragma unroll
        for (int k8 = 0; k8 < 8; k8++) {
            const int kb = k8 * 8;
            uint32_t af0 = Ps[(wrow + g    ) * ALDK + kb + tig    ];
            uint32_t af1 = Ps[(wrow + g + 8) * ALDK + kb + tig    ];
            uint32_t af2 = Ps[(wrow + g    ) * ALDK + kb + tig + 4];
            uint32_t af3 = Ps[(wrow + g + 8) * ALDK + kb + tig + 4];
            #pragma unroll
            for (int nt = 0; nt < 8; nt++) {
                uint32_t b0 = Vs[(kb + tig    ) * ALDV + nt * 8 + g];
                uint32_t b1 = Vs[(kb + tig + 4) * ALDV + nt * 8 + g];
                mma_tf32(o[nt][0], o[nt][1], o[nt][2], o[nt][3],
                         af0, af1, af2, af3, b0, b1);
            }
        }
        __syncthreads();
    }

    float inv0 = 1.0f / l0;
    float inv1 = 1.0f / l1;
    float* Or0 = O + base + (size_t)(q0 + wrow + g) * D_MODEL;
    float* Or1 = Or0 + 8 * D_MODEL;
    #pragma unroll
    for (int nt = 0; nt < 8; nt++) {
        int c = nt * 8 + tig * 2;
        *(float2*)&Or0[c] = make_float2(rtf(o[nt][0] * inv0), rtf(o[nt][1] * inv0));
        *(float2*)&Or1[c] = make_float2(rtf(o[nt][2] * inv1), rtf(o[nt][3] * inv1));
    }
}

// ---------------------------------------------------------------------------
// Launch
// ---------------------------------------------------------------------------
extern "C" void kernel_launch(void* const* d_in, const int* in_sizes, int n_in,
                              void* d_out, int out_size)
{
    const float* x  = (const float*)d_in[0];
    const float* Wq = (const float*)d_in[1];
    const float* Wk = (const float*)d_in[2];
    const float* Wv = (const float*)d_in[3];
    const float* Wo = (const float*)d_in[4];
    float* out = (float*)d_out;

    float *q, *k, *v, *o, *xr, *wr;
    cudaGetSymbolAddress((void**)&q,  g_q);
    cudaGetSymbolAddress((void**)&k,  g_k);
    cudaGetSymbolAddress((void**)&v,  g_v);
    cudaGetSymbolAddress((void**)&o,  g_o);
    cudaGetSymbolAddress((void**)&xr, g_xr);
    cudaGetSymbolAddress((void**)&wr, g_wr);

    cudaFuncSetAttribute(gemm_tf32_multi,
                         cudaFuncAttributeMaxDynamicSharedMemorySize,
                         GEMM_SMEM_BYTES);
    cudaFuncSetAttribute(attn_mma_kernel,
                         cudaFuncAttributeMaxDynamicSharedMemorySize,
                         ATTN_SMEM_BYTES);

    // 0) pre-round x + weights to tf32-exact fp32
    int n4 = N4_X + 4 * N4_W;
    round_inputs<<<n4 / 256, 256>>>(
        (const float4*)x, (const float4*)Wq, (const float4*)Wk,
        (const float4*)Wv, (const float4*)Wo, (float4*)xr, (float4*)wr);

    const size_t WSZ = (size_t)D_MODEL * D_MODEL;

    // 1) fused QKV projection (rounded outputs for attn's cp.async)
    dim3 qkv_grid(3 * (D_MODEL / GBN), MTOT / GBM);   // (24, 32)
    gemm_tf32_multi<<<qkv_grid, 128, GEMM_SMEM_BYTES>>>(
        xr, wr, wr + WSZ, wr + 2 * WSZ, q, k, v, MTOT, D_MODEL, D_MODEL, 1);

    // 2) attention
    dim3 attn_grid(SEQ / AQT, NUM_HEADS, BATCH);      // (16, 16, 2)
    attn_mma_kernel<<<attn_grid, 256, ATTN_SMEM_BYTES>>>(q, k, v, o);

    // 3) output projection (plain fp32 out)
    dim3 o_grid(D_MODEL / GBN, MTOT / GBM);           // (8, 32)
    gemm_tf32_multi<<<o_grid, 128, GEMM_SMEM_BYTES>>>(
        o, wr + 3 * WSZ, wr + 3 * WSZ, wr + 3 * WSZ, out, out, out,
        MTOT, D_MODEL, D_MODEL, 0);
}